// round 15
// baseline (speedup 1.0000x reference)
#include <cuda_runtime.h>
#include <cuda_fp16.h>
#include <cstdint>
#include <math.h>

#define NHALF 4096
#define NROWS 8192
#define D 256

#define BM 128
#define BN 64                        // per-group col tile
#define CSPLIT 2
#define NTG 32                       // col tiles per group (8192/2/2/64)

// ---------------- device globals (no allocs allowed) ----------------
__device__ __align__(16) float  g_zn[NROWS * D];   // fp32 rows (pos dot)
__device__ __align__(16) __half g_zh[NROWS * D];   // fp16 rows (MMA)
__device__ float g_denom[NROWS];
__device__ float g_acc[2];
__device__ unsigned int g_ticket;

// ---------------- PTX helpers (arch-portable sm_80+ forms only) ----------
__device__ __forceinline__ uint32_t smem_u32(const void* p) {
    uint32_t a;
    asm("{ .reg .u64 t; cvta.to.shared.u64 t, %1; cvt.u32.u64 %0, t; }" : "=r"(a) : "l"(p));
    return a;
}
#define CPASYNC16(dst, src) \
    asm volatile("cp.async.cg.shared.global [%0], [%1], 16;" :: "r"(dst), "l"(src))
#define CPCOMMIT() asm volatile("cp.async.commit_group;" ::: "memory")
#define CPWAIT(n)  asm volatile("cp.async.wait_group %0;" :: "n"(n) : "memory")
#define BARG(id)   asm volatile("bar.sync %0, 128;" :: "r"(id) : "memory")

#define LDSM4(r0, r1, r2, r3, a) \
    asm volatile("ldmatrix.sync.aligned.m8n8.x4.shared.b16 {%0,%1,%2,%3},[%4];" \
        : "=r"(r0), "=r"(r1), "=r"(r2), "=r"(r3) : "r"(a))

// fp16 inputs, fp32 accumulate
#define MMA16816(d, a, b) \
    asm volatile("mma.sync.aligned.m16n8k16.row.col.f32.f16.f16.f32 " \
        "{%0,%1,%2,%3},{%4,%5,%6,%7},{%8,%9},{%0,%1,%2,%3};" \
        : "+f"((d)[0]), "+f"((d)[1]), "+f"((d)[2]), "+f"((d)[3]) \
        : "r"((a)[0]), "r"((a)[1]), "r"((a)[2]), "r"((a)[3]), "r"((b)[0]), "r"((b)[1]))

__device__ __forceinline__ float ex2f(float x) {
    float y;
    asm("ex2.approx.f32 %0, %1;" : "=f"(y) : "f"(x));
    return y;
}

// ---------------------------------------------------------------------------
// K1: warp-per-row normalize (float4 + shfl-only reduce). 8 rows per block.
// ---------------------------------------------------------------------------
__global__ void k_normalize(const float* __restrict__ z_i,
                            const float* __restrict__ z_j) {
    int row = blockIdx.x * 8 + (threadIdx.x >> 5);
    int lane = threadIdx.x & 31;
    const float* src = (row < NHALF) ? (z_i + (size_t)row * D)
                                     : (z_j + (size_t)(row - NHALF) * D);
    float4 a0 = ((const float4*)src)[lane];
    float4 a1 = ((const float4*)src)[lane + 32];
    float ss = a0.x * a0.x + a0.y * a0.y + a0.z * a0.z + a0.w * a0.w
             + a1.x * a1.x + a1.y * a1.y + a1.z * a1.z + a1.w * a1.w;
#pragma unroll
    for (int o = 16; o; o >>= 1) ss += __shfl_xor_sync(0xffffffffu, ss, o);
    float inv = 1.0f / fmaxf(sqrtf(ss), 1e-8f);
    float4 n0 = make_float4(a0.x * inv, a0.y * inv, a0.z * inv, a0.w * inv);
    float4 n1 = make_float4(a1.x * inv, a1.y * inv, a1.z * inv, a1.w * inv);
    ((float4*)(g_zn + (size_t)row * D))[lane] = n0;
    ((float4*)(g_zn + (size_t)row * D))[lane + 32] = n1;
    __half2* h = (__half2*)(g_zh + (size_t)row * D);
    h[2 * lane]      = __floats2half2_rn(n0.x, n0.y);
    h[2 * lane + 1]  = __floats2half2_rn(n0.z, n0.w);
    h[2 * lane + 64] = __floats2half2_rn(n1.x, n1.y);
    h[2 * lane + 65] = __floats2half2_rn(n1.z, n1.w);
    if (lane == 0) {
        g_denom[row] = 0.f;
        if (row == 0) { g_acc[0] = 0.f; g_acc[1] = 0.f; g_ticket = 0u; }
    }
}

// ---------------------------------------------------------------------------
// SMEM: A 64KB, then 4 B buffers of 32KB (2 per group)
// ---------------------------------------------------------------------------
#define SM_B     65536
#define SM_BSTR  32768
#define SM_TOTAL (65536 + 4 * 32768)   // 192 KB

// 64-row fp16 B tile (32KB) loaded by ONE group's 128 threads
__device__ __forceinline__ void load_btile_async(uint32_t sdst, const char* gsrc, int gtid) {
#pragma unroll
    for (int i = 0; i < 16; i++) {
        int c = gtid + i * 128;           // 0..2047 16B chunks
        int r = c >> 5, cc = c & 31;
        uint32_t dst = sdst + r * 512 + ((cc ^ (r & 7)) << 4);
        CPASYNC16(dst, gsrc + (size_t)c * 16);
    }
}

// ---------------------------------------------------------------------------
// K2: HMMA sim GEMM, two decoupled 4-warp groups per CTA (private barriers +
// B buffers) so one group's MUFU epilogue hides under the other's mainloop.
// Warp tile 32x64 (unchanged). Grid (64, CSPLIT).
// ---------------------------------------------------------------------------
__global__ void __launch_bounds__(256) k_sim() {
    extern __shared__ char smem[];
    const int tid = threadIdx.x;
    const int wid = tid >> 5, lane = tid & 31;
    const int gid = wid >> 2;                 // group 0/1
    const int gtid = tid & 127;
    const int row0 = blockIdx.x * BM;
    const int colbase = blockIdx.y * (NROWS / CSPLIT) + gid * (NROWS / CSPLIT / 2);
    const int warp_row = (wid & 3) * 32;

    const uint32_t sbA = smem_u32(smem);
    const uint32_t sbB[2] = { sbA + SM_B + (gid * 2) * SM_BSTR,
                              sbA + SM_B + (gid * 2 + 1) * SM_BSTR };

    // prologue: A (all 256 threads) + per-group B0; drain; one full sync
    {
        const char* aptr = (const char*)(g_zh + (size_t)row0 * D);
#pragma unroll
        for (int i = 0; i < 16; i++) {
            int c = tid + i * 256;            // 0..4095
            int r = c >> 5, cc = c & 31;
            CPASYNC16(sbA + r * 512 + ((cc ^ (r & 7)) << 4), aptr + (size_t)c * 16);
        }
    }
    load_btile_async(sbB[0], (const char*)(g_zh + (size_t)colbase * D), gtid);
    CPCOMMIT();
    CPWAIT(0);
    __syncthreads();

    // ldmatrix address precompute (warp spans rows warp_row..+32, cols 0..64)
    uint32_t baseA[2]; int swA[2];
    const int hiA = lane >> 4;
#pragma unroll
    for (int mi = 0; mi < 2; mi++) {
        int rA = warp_row + mi * 16 + (lane & 15);
        baseA[mi] = sbA + rA * 512;
        swA[mi] = rA & 7;
    }
    uint32_t relB[4]; int swB[4];
    const int hiB = (lane >> 3) & 1;
#pragma unroll
    for (int np = 0; np < 4; np++) {
        int nB = np * 16 + (lane & 7) + ((lane & 16) >> 1);
        relB[np] = nB * 512;
        swB[np] = nB & 7;
    }

    const int grow = row0 + warp_row + (lane >> 2);   // global row of acc elt0
    const int lcq = 2 * (lane & 3);                   // col-in-tile of elt0
    const float K2E = 2.8853900817779268f;            // exp(2s) = 2^(s*K2E)
    const int bar = gid + 1;

    float rsum[2][2] = {{0.f, 0.f}, {0.f, 0.f}};

#pragma unroll 1
    for (int ct = 0; ct < NTG; ct++) {
        const uint32_t sbBt = sbB[ct & 1];
        if (ct + 1 < NTG) {
            load_btile_async(sbB[(ct + 1) & 1],
                             (const char*)(g_zh + (size_t)(colbase + (ct + 1) * BN) * D), gtid);
            CPCOMMIT();
            CPWAIT(1);
        } else {
            CPWAIT(0);
        }
        BARG(bar);

        float acc[2][8][4];
#pragma unroll
        for (int mi = 0; mi < 2; mi++)
#pragma unroll
            for (int ni = 0; ni < 8; ni++)
#pragma unroll
                for (int c = 0; c < 4; c++) acc[mi][ni][c] = 0.f;

#pragma unroll
        for (int s = 0; s < 16; s++) {
            uint32_t af[2][4];
#pragma unroll
            for (int mi = 0; mi < 2; mi++)
                LDSM4(af[mi][0], af[mi][1], af[mi][2], af[mi][3],
                      baseA[mi] + (((2 * s + hiA) ^ swA[mi]) << 4));
            uint32_t bfr[8][2];
#pragma unroll
            for (int np = 0; np < 4; np++) {
                uint32_t t0, t1, t2, t3;
                LDSM4(t0, t1, t2, t3,
                      sbBt + relB[np] + (((2 * s + hiB) ^ swB[np]) << 4));
                bfr[2 * np][0] = t0;     bfr[2 * np][1] = t1;
                bfr[2 * np + 1][0] = t2; bfr[2 * np + 1][1] = t3;
            }
#pragma unroll
            for (int mi = 0; mi < 2; mi++)
#pragma unroll
                for (int ni = 0; ni < 8; ni++)
                    MMA16816(acc[mi][ni], af[mi], bfr[ni]);
        }

        // epilogue: exp(2*sim) via MUFU; mask true diagonal (global compare)
        const int gc0 = colbase + ct * BN;
        const bool diag = (gc0 >= row0 && gc0 < row0 + BM);
#pragma unroll
        for (int mi = 0; mi < 2; mi++) {
#pragma unroll
            for (int ni = 0; ni < 8; ni++) {
                float e0 = ex2f(acc[mi][ni][0] * K2E);
                float e1 = ex2f(acc[mi][ni][1] * K2E);
                float e2 = ex2f(acc[mi][ni][2] * K2E);
                float e3 = ex2f(acc[mi][ni][3] * K2E);
                if (diag) {
                    int gr = grow + mi * 16;
                    int gc = gc0 + lcq + ni * 8;
                    if (gc == gr) e0 = 0.f;
                    if (gc + 1 == gr) e1 = 0.f;
                    if (gc == gr + 8) e2 = 0.f;
                    if (gc + 1 == gr + 8) e3 = 0.f;
                }
                rsum[mi][0] += e0 + e1;
                rsum[mi][1] += e2 + e3;
            }
        }
        BARG(bar);            // group warps done reading sbBt -> refill safe
    }

    // reduce: 4 lanes per row within warp; combine the 2 groups via smem;
    // one atomic per row per CTA. (Same shape as before: wid>>2 = group.)
    __syncthreads();
    float* sred = (float*)smem;   // A area reusable now
#pragma unroll
    for (int mi = 0; mi < 2; mi++)
#pragma unroll
        for (int h = 0; h < 2; h++) {
            float v = rsum[mi][h];
            v += __shfl_xor_sync(0xffffffffu, v, 1);
            v += __shfl_xor_sync(0xffffffffu, v, 2);
            if ((lane & 3) == 0 && gid == 1)
                sred[warp_row + mi * 16 + h * 8 + (lane >> 2)] = v;
            rsum[mi][h] = v;
        }
    __syncthreads();
    if (gid == 0 && (lane & 3) == 0) {
#pragma unroll
        for (int mi = 0; mi < 2; mi++)
#pragma unroll
            for (int h = 0; h < 2; h++) {
                int lr = warp_row + mi * 16 + h * 8 + (lane >> 2);
                atomicAdd(&g_denom[row0 + lr], rsum[mi][h] + sred[lr]);
            }
    }
}

// ---------------------------------------------------------------------------
// K3: fused positives + weighted loss + final division (atomic ticket).
// ---------------------------------------------------------------------------
#define LOSS_BLOCKS (NHALF * 32 / 256)

__global__ void k_loss(const float* __restrict__ w, float* __restrict__ out) {
    int gw = (blockIdx.x * blockDim.x + threadIdx.x) >> 5;   // pair id
    int lane = threadIdx.x & 31;
    const float4* a = (const float4*)(g_zn + (size_t)gw * D);
    const float4* b = (const float4*)(g_zn + (size_t)(gw + NHALF) * D);
    float s = 0.f;
#pragma unroll
    for (int p = 0; p < 2; p++) {
        float4 x = a[lane + p * 32];
        float4 y = b[lane + p * 32];
        s += x.x * y.x + x.y * y.y + x.z * y.z + x.w * y.w;
    }
#pragma unroll
    for (int o = 16; o; o >>= 1) s += __shfl_xor_sync(0xffffffffu, s, o);

    __shared__ float s_num[8], s_den[8];
    int wrp = threadIdx.x >> 5;
    if (lane == 0) {
        float wi = w[gw];
        s_num[wrp] = wi * (logf(g_denom[gw]) + logf(g_denom[gw + NHALF]) - 4.0f * s);
        s_den[wrp] = 2.0f * wi;
    }
    __syncthreads();
    if (threadIdx.x == 0) {
        float n = 0.f, d = 0.f;
#pragma unroll
        for (int j = 0; j < 8; j++) { n += s_num[j]; d += s_den[j]; }
        atomicAdd(&g_acc[0], n);
        atomicAdd(&g_acc[1], d);
        __threadfence();
        unsigned int t = atomicAdd(&g_ticket, 1u);
        if (t == LOSS_BLOCKS - 1) {
            volatile float* va = g_acc;
            out[0] = va[0] / va[1];
        }
    }
}

// ---------------------------------------------------------------------------
extern "C" void kernel_launch(void* const* d_in, const int* in_sizes, int n_in,
                              void* d_out, int out_size) {
    const float* z_i = (const float*)d_in[0];
    const float* z_j = (const float*)d_in[1];
    const float* w   = (const float*)d_in[2];
    float* out = (float*)d_out;

    cudaFuncSetAttribute(k_sim, cudaFuncAttributeMaxDynamicSharedMemorySize, SM_TOTAL);

    k_normalize<<<NROWS / 8, 256>>>(z_i, z_j);
    k_sim<<<dim3(NROWS / BM, CSPLIT), 256, SM_TOTAL>>>();
    k_loss<<<LOSS_BLOCKS, 256>>>(w, out);
}

// round 16
// speedup vs baseline: 1.1269x; 1.1269x over previous
#include <cuda_runtime.h>
#include <cuda_fp16.h>
#include <cstdint>
#include <math.h>

#define NHALF 4096
#define NROWS 8192
#define D 256

#define NSM 148
#define TOTTILES 4096                // 64 rowblocks x 64 coltiles

// ---------------- device globals (no allocs allowed) ----------------
__device__ __align__(16) float  g_zn[NROWS * D];   // fp32 rows (pos dot)
__device__ __align__(16) __half g_zh[NROWS * D];   // fp16 rows (MMA)
__device__ float g_denom[NROWS];
__device__ float g_acc[2];
__device__ unsigned int g_ticket;

// ---------------- PTX helpers (arch-portable sm_80+ forms only) ----------
__device__ __forceinline__ uint32_t smem_u32(const void* p) {
    uint32_t a;
    asm("{ .reg .u64 t; cvta.to.shared.u64 t, %1; cvt.u32.u64 %0, t; }" : "=r"(a) : "l"(p));
    return a;
}
#define CPASYNC16(dst, src) \
    asm volatile("cp.async.cg.shared.global [%0], [%1], 16;" :: "r"(dst), "l"(src))
#define CPCOMMIT() asm volatile("cp.async.commit_group;" ::: "memory")
#define CPWAIT(n)  asm volatile("cp.async.wait_group %0;" :: "n"(n) : "memory")

#define LDSM4(r0, r1, r2, r3, a) \
    asm volatile("ldmatrix.sync.aligned.m8n8.x4.shared.b16 {%0,%1,%2,%3},[%4];" \
        : "=r"(r0), "=r"(r1), "=r"(r2), "=r"(r3) : "r"(a))

// fp16 inputs, fp32 accumulate (measured-best mainloop shape)
#define MMA16816(d, a, b) \
    asm volatile("mma.sync.aligned.m16n8k16.row.col.f32.f16.f16.f32 " \
        "{%0,%1,%2,%3},{%4,%5,%6,%7},{%8,%9},{%0,%1,%2,%3};" \
        : "+f"((d)[0]), "+f"((d)[1]), "+f"((d)[2]), "+f"((d)[3]) \
        : "r"((a)[0]), "r"((a)[1]), "r"((a)[2]), "r"((a)[3]), "r"((b)[0]), "r"((b)[1]))

__device__ __forceinline__ float ex2f(float x) {
    float y;
    asm("ex2.approx.f32 %0, %1;" : "=f"(y) : "f"(x));
    return y;
}

// ---------------------------------------------------------------------------
// K1: warp-per-row normalize (float4 + shfl-only reduce). 8 rows per block.
// ---------------------------------------------------------------------------
__global__ void k_normalize(const float* __restrict__ z_i,
                            const float* __restrict__ z_j) {
    int row = blockIdx.x * 8 + (threadIdx.x >> 5);
    int lane = threadIdx.x & 31;
    const float* src = (row < NHALF) ? (z_i + (size_t)row * D)
                                     : (z_j + (size_t)(row - NHALF) * D);
    float4 a0 = ((const float4*)src)[lane];
    float4 a1 = ((const float4*)src)[lane + 32];
    float ss = a0.x * a0.x + a0.y * a0.y + a0.z * a0.z + a0.w * a0.w
             + a1.x * a1.x + a1.y * a1.y + a1.z * a1.z + a1.w * a1.w;
#pragma unroll
    for (int o = 16; o; o >>= 1) ss += __shfl_xor_sync(0xffffffffu, ss, o);
    float inv = 1.0f / fmaxf(sqrtf(ss), 1e-8f);
    float4 n0 = make_float4(a0.x * inv, a0.y * inv, a0.z * inv, a0.w * inv);
    float4 n1 = make_float4(a1.x * inv, a1.y * inv, a1.z * inv, a1.w * inv);
    ((float4*)(g_zn + (size_t)row * D))[lane] = n0;
    ((float4*)(g_zn + (size_t)row * D))[lane + 32] = n1;
    __half2* h = (__half2*)(g_zh + (size_t)row * D);
    h[2 * lane]      = __floats2half2_rn(n0.x, n0.y);
    h[2 * lane + 1]  = __floats2half2_rn(n0.z, n0.w);
    h[2 * lane + 64] = __floats2half2_rn(n1.x, n1.y);
    h[2 * lane + 65] = __floats2half2_rn(n1.z, n1.w);
    if (lane == 0) {
        g_denom[row] = 0.f;
        if (row == 0) { g_acc[0] = 0.f; g_acc[1] = 0.f; g_ticket = 0u; }
    }
}

// ---------------------------------------------------------------------------
// Async-copy one 128x256 fp16 tile (64KB) into XOR-swizzled SMEM.
// ---------------------------------------------------------------------------
__device__ __forceinline__ void load_tile_async(uint32_t sdst, const char* gsrc, int tid) {
#pragma unroll
    for (int i = 0; i < 16; i++) {
        int c = tid + i * 256;            // 0..4095
        int r = c >> 5, cc = c & 31;
        uint32_t dst = sdst + r * 512 + ((cc ^ (r & 7)) << 4);
        CPASYNC16(dst, gsrc + (size_t)c * 16);
    }
}

// SMEM: A 64KB + 2x B 64KB + 512B reduce scratch
#define SM_SRED  196608
#define SM_TOTAL (196608 + 512)

// ---------------------------------------------------------------------------
// K2: HMMA sim GEMM over 148 balanced contiguous tile-slices (row-major tile
// list) — one full wave on all SMs, no wave quantization. A reloaded on
// rowblock switch (<=1 per CTA); rsum flushed per rowblock.
// ---------------------------------------------------------------------------
__global__ void __launch_bounds__(256) k_sim() {
    extern __shared__ char smem[];
    const int tid = threadIdx.x;
    const int wid = tid >> 5, lane = tid & 31;
    const int warp_row = (wid & 3) * 32;
    const int warp_col = (wid >> 2) * 64;

    const uint32_t sbA = smem_u32(smem);
    const uint32_t sbB[2] = { sbA + 65536, sbA + 131072 };
    float* sred = (float*)(smem + SM_SRED);

    const int t0 = ((int)blockIdx.x * TOTTILES) / NSM;
    const int t1 = (((int)blockIdx.x + 1) * TOTTILES) / NSM;
    int rb = t0 >> 6;                         // current rowblock

    // prologue: A(rb) + B(t0) as one group
    load_tile_async(sbA, (const char*)(g_zh + (size_t)rb * 128 * D), tid);
    load_tile_async(sbB[0], (const char*)(g_zh + (size_t)(t0 & 63) * 128 * D), tid);
    CPCOMMIT();

    // ldmatrix address precompute
    uint32_t baseA[2]; int swA[2];
    const int hiA = lane >> 4;
#pragma unroll
    for (int mi = 0; mi < 2; mi++) {
        int rA = warp_row + mi * 16 + (lane & 15);
        baseA[mi] = sbA + rA * 512;
        swA[mi] = rA & 7;
    }
    uint32_t relB[4]; int swB[4];
    const int hiB = (lane >> 3) & 1;
#pragma unroll
    for (int np = 0; np < 4; np++) {
        int nB = warp_col + np * 16 + (lane & 7) + ((lane & 16) >> 1);
        relB[np] = nB * 512;
        swB[np] = nB & 7;
    }

    const int lr0 = warp_row + (lane >> 2);      // local row of acc elt0
    const int lc0 = warp_col + 2 * (lane & 3);   // local col of acc elt0
    const float K2E = 2.8853900817779268f;       // exp(2s) = 2^(s*K2E)

    float rsum[2][2] = {{0.f, 0.f}, {0.f, 0.f}};
    int nbuf = 0;

#pragma unroll 1
    for (int t = t0; t < t1; t++) {
        const int ct = t & 63;
        const uint32_t sbBt = sbB[nbuf];
        if (t + 1 < t1) {
            load_tile_async(sbB[nbuf ^ 1],
                            (const char*)(g_zh + (size_t)((t + 1) & 63) * 128 * D), tid);
            CPCOMMIT();
            CPWAIT(1);
        } else {
            CPWAIT(0);
        }
        __syncthreads();

        float acc[2][8][4];
#pragma unroll
        for (int mi = 0; mi < 2; mi++)
#pragma unroll
            for (int ni = 0; ni < 8; ni++)
#pragma unroll
                for (int c = 0; c < 4; c++) acc[mi][ni][c] = 0.f;

#pragma unroll
        for (int s = 0; s < 16; s++) {
            uint32_t af[2][4];
#pragma unroll
            for (int mi = 0; mi < 2; mi++)
                LDSM4(af[mi][0], af[mi][1], af[mi][2], af[mi][3],
                      baseA[mi] + (((2 * s + hiA) ^ swA[mi]) << 4));
            uint32_t bfr[8][2];
#pragma unroll
            for (int np = 0; np < 4; np++) {
                uint32_t u0, u1, u2, u3;
                LDSM4(u0, u1, u2, u3,
                      sbBt + relB[np] + (((2 * s + hiB) ^ swB[np]) << 4));
                bfr[2 * np][0] = u0;     bfr[2 * np][1] = u1;
                bfr[2 * np + 1][0] = u2; bfr[2 * np + 1][1] = u3;
            }
#pragma unroll
            for (int mi = 0; mi < 2; mi++)
#pragma unroll
                for (int ni = 0; ni < 8; ni++)
                    MMA16816(acc[mi][ni], af[mi], bfr[ni]);
        }

        // epilogue: exp(2*sim) via MUFU; diag tile iff ct == rb
        const bool diag = (ct == rb);
#pragma unroll
        for (int mi = 0; mi < 2; mi++) {
#pragma unroll
            for (int ni = 0; ni < 8; ni++) {
                float e0 = ex2f(acc[mi][ni][0] * K2E);
                float e1 = ex2f(acc[mi][ni][1] * K2E);
                float e2 = ex2f(acc[mi][ni][2] * K2E);
                float e3 = ex2f(acc[mi][ni][3] * K2E);
                if (diag) {
                    int gr = lr0 + mi * 16;
                    int gc = lc0 + ni * 8;
                    if (gc == gr) e0 = 0.f;
                    if (gc + 1 == gr) e1 = 0.f;
                    if (gc == gr + 8) e2 = 0.f;
                    if (gc + 1 == gr + 8) e3 = 0.f;
                }
                rsum[mi][0] += e0 + e1;
                rsum[mi][1] += e2 + e3;
            }
        }

        const bool last = (t + 1 == t1);
        const bool rbSwitch = !last && (((t + 1) >> 6) != rb);
        if (rbSwitch || last) {
            // flush rsum for rowblock rb (reduce + one atomic per row)
            __syncthreads();                   // all warps done with A + epilogue
#pragma unroll
            for (int mi = 0; mi < 2; mi++)
#pragma unroll
                for (int h = 0; h < 2; h++) {
                    float v = rsum[mi][h];
                    v += __shfl_xor_sync(0xffffffffu, v, 1);
                    v += __shfl_xor_sync(0xffffffffu, v, 2);
                    if ((lane & 3) == 0 && (wid >> 2) == 1)
                        sred[warp_row + mi * 16 + h * 8 + (lane >> 2)] = v;
                    rsum[mi][h] = v;
                }
            __syncthreads();
            if ((wid >> 2) == 0 && (lane & 3) == 0) {
#pragma unroll
                for (int mi = 0; mi < 2; mi++)
#pragma unroll
                    for (int h = 0; h < 2; h++) {
                        int lr = warp_row + mi * 16 + h * 8 + (lane >> 2);
                        atomicAdd(&g_denom[rb * 128 + lr], rsum[mi][h] + sred[lr]);
                    }
            }
            rsum[0][0] = rsum[0][1] = rsum[1][0] = rsum[1][1] = 0.f;
            if (rbSwitch) {
                rb = (t + 1) >> 6;
                load_tile_async(sbA, (const char*)(g_zh + (size_t)rb * 128 * D), tid);
                CPCOMMIT();
                CPWAIT(0);                     // drains A and pending B group
                __syncthreads();
            }
        } else {
            __syncthreads();                   // release sbBt for next prefetch
        }
        nbuf ^= 1;
    }
}

// ---------------------------------------------------------------------------
// K3: fused positives + weighted loss + final division (atomic ticket).
// ---------------------------------------------------------------------------
#define LOSS_BLOCKS (NHALF * 32 / 256)

__global__ void k_loss(const float* __restrict__ w, float* __restrict__ out) {
    int gw = (blockIdx.x * blockDim.x + threadIdx.x) >> 5;   // pair id
    int lane = threadIdx.x & 31;
    const float4* a = (const float4*)(g_zn + (size_t)gw * D);
    const float4* b = (const float4*)(g_zn + (size_t)(gw + NHALF) * D);
    float s = 0.f;
#pragma unroll
    for (int p = 0; p < 2; p++) {
        float4 x = a[lane + p * 32];
        float4 y = b[lane + p * 32];
        s += x.x * y.x + x.y * y.y + x.z * y.z + x.w * y.w;
    }
#pragma unroll
    for (int o = 16; o; o >>= 1) s += __shfl_xor_sync(0xffffffffu, s, o);

    __shared__ float s_num[8], s_den[8];
    int wrp = threadIdx.x >> 5;
    if (lane == 0) {
        float wi = w[gw];
        s_num[wrp] = wi * (logf(g_denom[gw]) + logf(g_denom[gw + NHALF]) - 4.0f * s);
        s_den[wrp] = 2.0f * wi;
    }
    __syncthreads();
    if (threadIdx.x == 0) {
        float n = 0.f, d = 0.f;
#pragma unroll
        for (int j = 0; j < 8; j++) { n += s_num[j]; d += s_den[j]; }
        atomicAdd(&g_acc[0], n);
        atomicAdd(&g_acc[1], d);
        __threadfence();
        unsigned int t = atomicAdd(&g_ticket, 1u);
        if (t == LOSS_BLOCKS - 1) {
            volatile float* va = g_acc;
            out[0] = va[0] / va[1];
        }
    }
}

// ---------------------------------------------------------------------------
extern "C" void kernel_launch(void* const* d_in, const int* in_sizes, int n_in,
                              void* d_out, int out_size) {
    const float* z_i = (const float*)d_in[0];
    const float* z_j = (const float*)d_in[1];
    const float* w   = (const float*)d_in[2];
    float* out = (float*)d_out;

    cudaFuncSetAttribute(k_sim, cudaFuncAttributeMaxDynamicSharedMemorySize, SM_TOTAL);

    k_normalize<<<NROWS / 8, 256>>>(z_i, z_j);
    k_sim<<<NSM, 256, SM_TOTAL>>>();
    k_loss<<<LOSS_BLOCKS, 256>>>(w, out);
}

// round 17
// speedup vs baseline: 1.1425x; 1.0139x over previous
#include <cuda_runtime.h>
#include <cuda_fp16.h>
#include <cstdint>
#include <math.h>

#define NHALF 4096
#define NROWS 8192
#define D 256
#define TOTTILES 4096                // 64 rowblocks x 64 coltiles

// ---------------- device globals (no allocs allowed) ----------------
__device__ __align__(16) float  g_zn[NROWS * D];   // fp32 rows (pos dot)
__device__ __align__(16) __half g_zh[NROWS * D];   // fp16 rows (MMA)
__device__ float g_denom[NROWS];
__device__ float g_acc[2];
__device__ unsigned int g_ticket;
__device__ unsigned int g_sync;      // monotonic grid-barrier counter

// ---------------- PTX helpers (arch-portable sm_80+ forms only) ----------
__device__ __forceinline__ uint32_t smem_u32(const void* p) {
    uint32_t a;
    asm("{ .reg .u64 t; cvta.to.shared.u64 t, %1; cvt.u32.u64 %0, t; }" : "=r"(a) : "l"(p));
    return a;
}
#define CPASYNC16(dst, src) \
    asm volatile("cp.async.cg.shared.global [%0], [%1], 16;" :: "r"(dst), "l"(src))
#define CPCOMMIT() asm volatile("cp.async.commit_group;" ::: "memory")
#define CPWAIT(n)  asm volatile("cp.async.wait_group %0;" :: "n"(n) : "memory")

#define LDSM4(r0, r1, r2, r3, a) \
    asm volatile("ldmatrix.sync.aligned.m8n8.x4.shared.b16 {%0,%1,%2,%3},[%4];" \
        : "=r"(r0), "=r"(r1), "=r"(r2), "=r"(r3) : "r"(a))

// fp16 inputs, fp32 accumulate (measured-best mainloop shape)
#define MMA16816(d, a, b) \
    asm volatile("mma.sync.aligned.m16n8k16.row.col.f32.f16.f16.f32 " \
        "{%0,%1,%2,%3},{%4,%5,%6,%7},{%8,%9},{%0,%1,%2,%3};" \
        : "+f"((d)[0]), "+f"((d)[1]), "+f"((d)[2]), "+f"((d)[3]) \
        : "r"((a)[0]), "r"((a)[1]), "r"((a)[2]), "r"((a)[3]), "r"((b)[0]), "r"((b)[1]))

__device__ __forceinline__ float ex2f(float x) {
    float y;
    asm("ex2.approx.f32 %0, %1;" : "=f"(y) : "f"(x));
    return y;
}

// ---------------------------------------------------------------------------
// Async-copy one 128x256 fp16 tile (64KB) into XOR-swizzled SMEM.
// ---------------------------------------------------------------------------
__device__ __forceinline__ void load_tile_async(uint32_t sdst, const char* gsrc, int tid) {
#pragma unroll
    for (int i = 0; i < 16; i++) {
        int c = tid + i * 256;            // 0..4095
        int r = c >> 5, cc = c & 31;
        uint32_t dst = sdst + r * 512 + ((cc ^ (r & 7)) << 4);
        CPASYNC16(dst, gsrc + (size_t)c * 16);
    }
}

// SMEM: A 64KB + 2x B 64KB + 512B reduce scratch
#define SM_SRED  196608
#define SM_TOTAL (196608 + 512)

// ---------------------------------------------------------------------------
// K2: persistent fused kernel. Phase 0: normalize this CTA's row-slice
// (fp32 + fp16 copies, zero accumulators), grid spin-barrier (monotonic
// counter, replay-safe). Phase 1: HMMA sim GEMM over a balanced contiguous
// tile-slice (one wave on all SMs).
// ---------------------------------------------------------------------------
__global__ void __launch_bounds__(256) k_sim(const float* __restrict__ z_i,
                                             const float* __restrict__ z_j) {
    extern __shared__ char smem[];
    const int tid = threadIdx.x;
    const int wid = tid >> 5, lane = tid & 31;
    const int nsm = gridDim.x;
    const int bid = blockIdx.x;
    const int warp_row = (wid & 3) * 32;
    const int warp_col = (wid >> 2) * 64;

    // ---- phase 0: normalize rows [r0, r1) ----
    {
        const int r0 = (bid * NROWS) / nsm;
        const int r1 = ((bid + 1) * NROWS) / nsm;
        for (int row = r0 + wid; row < r1; row += 8) {
            const float* src = (row < NHALF) ? (z_i + (size_t)row * D)
                                             : (z_j + (size_t)(row - NHALF) * D);
            float4 a0 = ((const float4*)src)[lane];
            float4 a1 = ((const float4*)src)[lane + 32];
            float ss = a0.x * a0.x + a0.y * a0.y + a0.z * a0.z + a0.w * a0.w
                     + a1.x * a1.x + a1.y * a1.y + a1.z * a1.z + a1.w * a1.w;
#pragma unroll
            for (int o = 16; o; o >>= 1) ss += __shfl_xor_sync(0xffffffffu, ss, o);
            float inv = 1.0f / fmaxf(sqrtf(ss), 1e-8f);
            float4 n0 = make_float4(a0.x * inv, a0.y * inv, a0.z * inv, a0.w * inv);
            float4 n1 = make_float4(a1.x * inv, a1.y * inv, a1.z * inv, a1.w * inv);
            ((float4*)(g_zn + (size_t)row * D))[lane] = n0;
            ((float4*)(g_zn + (size_t)row * D))[lane + 32] = n1;
            __half2* h = (__half2*)(g_zh + (size_t)row * D);
            h[2 * lane]      = __floats2half2_rn(n0.x, n0.y);
            h[2 * lane + 1]  = __floats2half2_rn(n0.z, n0.w);
            h[2 * lane + 64] = __floats2half2_rn(n1.x, n1.y);
            h[2 * lane + 65] = __floats2half2_rn(n1.z, n1.w);
            if (lane == 0) g_denom[row] = 0.f;
        }
        if (bid == 0 && tid == 0) { g_acc[0] = 0.f; g_acc[1] = 0.f; g_ticket = 0u; }
    }

    // ---- grid spin-barrier (monotonic counter; all CTAs resident) ----
    {
        __shared__ unsigned s_target;
        __threadfence();
        __syncthreads();
        if (tid == 0) {
            unsigned my = atomicAdd(&g_sync, 1u);
            unsigned target = (my / (unsigned)nsm + 1u) * (unsigned)nsm;
            while (*(volatile unsigned*)&g_sync < target) { }
            s_target = target;          // consume to keep the spin live
        }
        __syncthreads();
        __threadfence();
        (void)s_target;
    }

    // ---- phase 1: GEMM over tile-slice [t0, t1) ----
    const uint32_t sbA = smem_u32(smem);
    const uint32_t sbB[2] = { sbA + 65536, sbA + 131072 };
    float* sred = (float*)(smem + SM_SRED);

    const int t0 = (bid * TOTTILES) / nsm;
    const int t1 = ((bid + 1) * TOTTILES) / nsm;
    int rb = t0 >> 6;

    load_tile_async(sbA, (const char*)(g_zh + (size_t)rb * 128 * D), tid);
    load_tile_async(sbB[0], (const char*)(g_zh + (size_t)(t0 & 63) * 128 * D), tid);
    CPCOMMIT();

    uint32_t baseA[2]; int swA[2];
    const int hiA = lane >> 4;
#pragma unroll
    for (int mi = 0; mi < 2; mi++) {
        int rA = warp_row + mi * 16 + (lane & 15);
        baseA[mi] = sbA + rA * 512;
        swA[mi] = rA & 7;
    }
    uint32_t relB[4]; int swB[4];
    const int hiB = (lane >> 3) & 1;
#pragma unroll
    for (int np = 0; np < 4; np++) {
        int nB = warp_col + np * 16 + (lane & 7) + ((lane & 16) >> 1);
        relB[np] = nB * 512;
        swB[np] = nB & 7;
    }

    const int lr0 = warp_row + (lane >> 2);
    const int lc0 = warp_col + 2 * (lane & 3);
    const float K2E = 2.8853900817779268f;       // exp(2s) = 2^(s*K2E)

    float rsum[2][2] = {{0.f, 0.f}, {0.f, 0.f}};
    int nbuf = 0;

#pragma unroll 1
    for (int t = t0; t < t1; t++) {
        const int ct = t & 63;
        const uint32_t sbBt = sbB[nbuf];
        if (t + 1 < t1) {
            load_tile_async(sbB[nbuf ^ 1],
                            (const char*)(g_zh + (size_t)((t + 1) & 63) * 128 * D), tid);
            CPCOMMIT();
            CPWAIT(1);
        } else {
            CPWAIT(0);
        }
        __syncthreads();

        float acc[2][8][4];
#pragma unroll
        for (int mi = 0; mi < 2; mi++)
#pragma unroll
            for (int ni = 0; ni < 8; ni++)
#pragma unroll
                for (int c = 0; c < 4; c++) acc[mi][ni][c] = 0.f;

#pragma unroll
        for (int s = 0; s < 16; s++) {
            uint32_t af[2][4];
#pragma unroll
            for (int mi = 0; mi < 2; mi++)
                LDSM4(af[mi][0], af[mi][1], af[mi][2], af[mi][3],
                      baseA[mi] + (((2 * s + hiA) ^ swA[mi]) << 4));
            uint32_t bfr[8][2];
#pragma unroll
            for (int np = 0; np < 4; np++) {
                uint32_t u0, u1, u2, u3;
                LDSM4(u0, u1, u2, u3,
                      sbBt + relB[np] + (((2 * s + hiB) ^ swB[np]) << 4));
                bfr[2 * np][0] = u0;     bfr[2 * np][1] = u1;
                bfr[2 * np + 1][0] = u2; bfr[2 * np + 1][1] = u3;
            }
#pragma unroll
            for (int mi = 0; mi < 2; mi++)
#pragma unroll
                for (int ni = 0; ni < 8; ni++)
                    MMA16816(acc[mi][ni], af[mi], bfr[ni]);
        }

        const bool diag = (ct == rb);
#pragma unroll
        for (int mi = 0; mi < 2; mi++) {
#pragma unroll
            for (int ni = 0; ni < 8; ni++) {
                float e0 = ex2f(acc[mi][ni][0] * K2E);
                float e1 = ex2f(acc[mi][ni][1] * K2E);
                float e2 = ex2f(acc[mi][ni][2] * K2E);
                float e3 = ex2f(acc[mi][ni][3] * K2E);
                if (diag) {
                    int gr = lr0 + mi * 16;
                    int gc = lc0 + ni * 8;
                    if (gc == gr) e0 = 0.f;
                    if (gc + 1 == gr) e1 = 0.f;
                    if (gc == gr + 8) e2 = 0.f;
                    if (gc + 1 == gr + 8) e3 = 0.f;
                }
                rsum[mi][0] += e0 + e1;
                rsum[mi][1] += e2 + e3;
            }
        }

        const bool last = (t + 1 == t1);
        const bool rbSwitch = !last && (((t + 1) >> 6) != rb);
        if (rbSwitch || last) {
            __syncthreads();
#pragma unroll
            for (int mi = 0; mi < 2; mi++)
#pragma unroll
                for (int h = 0; h < 2; h++) {
                    float v = rsum[mi][h];
                    v += __shfl_xor_sync(0xffffffffu, v, 1);
                    v += __shfl_xor_sync(0xffffffffu, v, 2);
                    if ((lane & 3) == 0 && (wid >> 2) == 1)
                        sred[warp_row + mi * 16 + h * 8 + (lane >> 2)] = v;
                    rsum[mi][h] = v;
                }
            __syncthreads();
            if ((wid >> 2) == 0 && (lane & 3) == 0) {
#pragma unroll
                for (int mi = 0; mi < 2; mi++)
#pragma unroll
                    for (int h = 0; h < 2; h++) {
                        int lr = warp_row + mi * 16 + h * 8 + (lane >> 2);
                        atomicAdd(&g_denom[rb * 128 + lr], rsum[mi][h] + sred[lr]);
                    }
            }
            rsum[0][0] = rsum[0][1] = rsum[1][0] = rsum[1][1] = 0.f;
            if (rbSwitch) {
                rb = (t + 1) >> 6;
                load_tile_async(sbA, (const char*)(g_zh + (size_t)rb * 128 * D), tid);
                CPCOMMIT();
                CPWAIT(0);
                __syncthreads();
            }
        } else {
            __syncthreads();
        }
        nbuf ^= 1;
    }
}

// ---------------------------------------------------------------------------
// K3: fused positives + weighted loss + final division (atomic ticket).
// ---------------------------------------------------------------------------
#define LOSS_BLOCKS (NHALF * 32 / 256)

__global__ void k_loss(const float* __restrict__ w, float* __restrict__ out) {
    int gw = (blockIdx.x * blockDim.x + threadIdx.x) >> 5;   // pair id
    int lane = threadIdx.x & 31;
    const float4* a = (const float4*)(g_zn + (size_t)gw * D);
    const float4* b = (const float4*)(g_zn + (size_t)(gw + NHALF) * D);
    float s = 0.f;
#pragma unroll
    for (int p = 0; p < 2; p++) {
        float4 x = a[lane + p * 32];
        float4 y = b[lane + p * 32];
        s += x.x * y.x + x.y * y.y + x.z * y.z + x.w * y.w;
    }
#pragma unroll
    for (int o = 16; o; o >>= 1) s += __shfl_xor_sync(0xffffffffu, s, o);

    __shared__ float s_num[8], s_den[8];
    int wrp = threadIdx.x >> 5;
    if (lane == 0) {
        float wi = w[gw];
        s_num[wrp] = wi * (logf(g_denom[gw]) + logf(g_denom[gw + NHALF]) - 4.0f * s);
        s_den[wrp] = 2.0f * wi;
    }
    __syncthreads();
    if (threadIdx.x == 0) {
        float n = 0.f, d = 0.f;
#pragma unroll
        for (int j = 0; j < 8; j++) { n += s_num[j]; d += s_den[j]; }
        atomicAdd(&g_acc[0], n);
        atomicAdd(&g_acc[1], d);
        __threadfence();
        unsigned int t = atomicAdd(&g_ticket, 1u);
        if (t == LOSS_BLOCKS - 1) {
            volatile float* va = g_acc;
            out[0] = va[0] / va[1];
        }
    }
}

// ---------------------------------------------------------------------------
extern "C" void kernel_launch(void* const* d_in, const int* in_sizes, int n_in,
                              void* d_out, int out_size) {
    const float* z_i = (const float*)d_in[0];
    const float* z_j = (const float*)d_in[1];
    const float* w   = (const float*)d_in[2];
    float* out = (float*)d_out;

    int nsm = 0;
    cudaDeviceGetAttribute(&nsm, cudaDevAttrMultiProcessorCount, 0);
    if (nsm <= 0) nsm = 148;

    cudaFuncSetAttribute(k_sim, cudaFuncAttributeMaxDynamicSharedMemorySize, SM_TOTAL);

    k_sim<<<nsm, 256, SM_TOTAL>>>(z_i, z_j);
    k_loss<<<LOSS_BLOCKS, 256>>>(w, out);
}